// round 14
// baseline (speedup 1.0000x reference)
#include <cuda_runtime.h>

#define BB 2
#define DD 1536
#define LL 2048
#define NN 16
#define TL 128          // timesteps per tile (16 lanes * 8)
#define JJ 8            // items per lane
#define WARPS 4         // warps per block; 2 d-channels per warp
#define CHB  (WARPS*2)  // channels per block = 8
#define NT (LL / TL)    // 16 tiles

typedef unsigned long long ull;

__device__ __forceinline__ float ex2f(float x) {
    float r; asm("ex2.approx.f32 %0, %1;" : "=f"(r) : "f"(x)); return r;
}
__device__ __forceinline__ float lg2f(float x) {
    float r; asm("lg2.approx.f32 %0, %1;" : "=f"(r) : "f"(x)); return r;
}
__device__ __forceinline__ float tanhf_a(float x) {
    float r; asm("tanh.approx.f32 %0, %1;" : "=f"(r) : "f"(x)); return r;
}

__device__ __forceinline__ ull pk(float lo, float hi) {
    ull r; asm("mov.b64 %0, {%1, %2};" : "=l"(r) : "f"(lo), "f"(hi)); return r;
}
__device__ __forceinline__ float lo2(ull a) {
    float x, y; asm("mov.b64 {%0, %1}, %2;" : "=f"(x), "=f"(y) : "l"(a)); return x;
}
__device__ __forceinline__ float hi2(ull a) {
    float x, y; asm("mov.b64 {%0, %1}, %2;" : "=f"(x), "=f"(y) : "l"(a)); return y;
}
__device__ __forceinline__ ull mul2(ull a, ull b) {
    ull r; asm("mul.rn.f32x2 %0, %1, %2;" : "=l"(r) : "l"(a), "l"(b)); return r;
}

// L2-cached global->shared async copy (.cg: bypass L1)
__device__ __forceinline__ void cp16(unsigned saddr, const void* gaddr) {
    asm volatile("cp.async.cg.shared.global [%0], [%1], 16;\n" :: "r"(saddr), "l"(gaddr));
}

// XOR swizzle on float4-vector index within a 32-vec (128-float) row:
// makes the stride-2 LDS.128 pattern phase-conflict-free.
__device__ __forceinline__ int swz(int v) { return v ^ ((v >> 3) & 7); }

#define L2E 1.4426950408889634f
#define LN2 0.6931471805599453f

__global__ __launch_bounds__(128, 6) void ssm_scan_kernel(
    const float* __restrict__ x_g, const float* __restrict__ dt_g,
    const float* __restrict__ A_g, const float* __restrict__ B_g,
    const float* __restrict__ C_g, const float* __restrict__ D_g,
    const float* __restrict__ z_g, const float* __restrict__ db_g,
    float* __restrict__ out_g)
{
    extern __shared__ float4 smem_dyn[];
    // buf0: [0..512) Bs, [512..1024) Cs ; buf1: [1024..2048)
    float2* ahc = (float2*)(smem_dyn + 2048);   // [w][seg][n] = {A_raw, carry}

    const int b     = blockIdx.y;
    const int w     = threadIdx.x >> 5;
    const int lane  = threadIdx.x & 31;
    const int seg   = lane >> 4;         // which of the 2 channels in this warp
    const int slane = lane & 15;         // lane within the 16-lane segment
    const int d     = blockIdx.x * CHB + w * 2 + seg;
    const int tid   = threadIdx.x;

    const float* xp  = x_g  + (size_t)(b * DD + d) * LL;
    const float* dtp = dt_g + (size_t)(b * DD + d) * LL;
    const float* zp  = z_g  + (size_t)(b * DD + d) * LL;
    float*       op  = out_g + (size_t)(b * DD + d) * LL;

    const float4* Bg4 = (const float4*)(B_g + (size_t)b * NN * LL);
    const float4* Cg4 = (const float4*)(C_g + (size_t)b * NN * LL);

    // Every lane initializes one {A,carry} entry: its segment's entry for n=slane.
    {
        float2 v; v.x = A_g[d * NN + slane]; v.y = 0.0f;
        ahc[w * 32 + seg * 16 + slane] = v;
    }
    const float db = db_g[d];
    const float Dd = D_g[d];
    const float dbl2e = db * L2E;

    const int sv0 = swz(2 * slane);
    const int sv1 = swz(2 * slane + 1);

    // Prologue: stage tile 0 into buffer 0 via cp.async
    {
#pragma unroll
        for (int k = 0; k < 4; k++) {
            int v  = tid + k * 128;      // 0..511
            int n  = v >> 5;
            int vc = v & 31;
            unsigned sb = (unsigned)__cvta_generic_to_shared(&smem_dyn[n * 32 + swz(vc)]);
            unsigned sc = (unsigned)__cvta_generic_to_shared(&smem_dyn[512 + n * 32 + swz(vc)]);
            cp16(sb, Bg4 + n * (LL / 4) + vc);
            cp16(sc, Cg4 + n * (LL / 4) + vc);
        }
        asm volatile("cp.async.commit_group;\n" ::: "memory");
    }

    for (int t = 0; t < NT; t++) {
        const int l0 = t * TL;
        const int buf = (t & 1) * 1024;

        asm volatile("cp.async.wait_group 0;\n" ::: "memory");
        __syncthreads();   // staged data visible; prev compute done on other buffer

        // Stage tile t+1 into the other buffer (overlaps with compute)
        if (t + 1 < NT) {
            const int nb = ((t + 1) & 1) * 1024;
            const int g0 = (t + 1) * (TL / 4);
#pragma unroll
            for (int k = 0; k < 4; k++) {
                int v  = tid + k * 128;
                int n  = v >> 5;
                int vc = v & 31;
                unsigned sb = (unsigned)__cvta_generic_to_shared(&smem_dyn[nb + n * 32 + swz(vc)]);
                unsigned sc = (unsigned)__cvta_generic_to_shared(&smem_dyn[nb + 512 + n * 32 + swz(vc)]);
                cp16(sb, Bg4 + n * (LL / 4) + g0 + vc);
                cp16(sc, Cg4 + n * (LL / 4) + g0 + vc);
            }
            asm volatile("cp.async.commit_group;\n" ::: "memory");
        }

        const float4* Bs = smem_dyn + buf;
        const float4* Cs = smem_dyn + buf + 512;

        // Per-lane loads for its 8 contiguous timesteps of ITS channel
        const int base = l0 + slane * JJ;
        float4 t0 = *(const float4*)(dtp + base);
        float4 t1 = *(const float4*)(dtp + base + 4);
        float4 x0 = *(const float4*)(xp + base);
        float4 x1 = *(const float4*)(xp + base + 4);

        float q[JJ], y[JJ], qs;
        ull du2[4];
        {
            float xv[JJ] = {x0.x, x0.y, x0.z, x0.w, x1.x, x1.y, x1.z, x1.w};
            float dv[JJ] = {t0.x, t0.y, t0.z, t0.w, t1.x, t1.y, t1.z, t1.w};
#pragma unroll
            for (int j = 0; j < JJ; j++) {
                // softplus in log2 domain: q = log2(1 + 2^((dv+db)*log2e))
                q[j] = lg2f(1.0f + ex2f(fmaf(dv[j], L2E, dbl2e)));
                y[j] = 0.0f;
            }
            qs = (q[0] + q[1]) + (q[2] + q[3]) + ((q[4] + q[5]) + (q[6] + q[7]));
#pragma unroll
            for (int p = 0; p < 4; p++)
                du2[p] = pk(q[2 * p] * LN2 * xv[2 * p],
                            q[2 * p + 1] * LN2 * xv[2 * p + 1]);
        }

#pragma unroll
        for (int n = 0; n < NN; n++) {
            const float2 ah  = ahc[w * 32 + seg * 16 + n];  // {A_raw, carry} for MY channel
            const float  Ar  = ah.x;
            const float  hcn = ah.y;

            float4 bv0 = Bs[n * 32 + sv0];   // both segments read same addrs -> broadcast
            float4 bv1 = Bs[n * 32 + sv1];
            ull Bv2[4] = {((ull*)&bv0)[0], ((ull*)&bv0)[1], ((ull*)&bv1)[0], ((ull*)&bv1)[1]};

            float a_[JJ], duB[JJ];
#pragma unroll
            for (int p = 0; p < 4; p++) {
                ull duB2 = mul2(du2[p], Bv2[p]);
                duB[2 * p]     = lo2(duB2);
                duB[2 * p + 1] = hi2(duB2);
            }
#pragma unroll
            for (int j = 0; j < JJ; j++) a_[j] = ex2f(q[j] * Ar);

            // Phase A: b-aggregate chain; a-aggregate via one ex2.
            const float seed = (slane == 0) ? hcn : 0.0f;
            float acr = ex2f(qs * Ar);
            float bcr = fmaf(a_[0], seed, duB[0]);
#pragma unroll
            for (int j = 1; j < JJ; j++)
                bcr = fmaf(a_[j], bcr, duB[j]);

            // Phase B: segmented (width=16) inclusive scan; last round b-only.
#pragma unroll
            for (int off = 1; off < 8; off <<= 1) {
                float ap = __shfl_up_sync(0xffffffffu, acr, off, 16);
                float bp = __shfl_up_sync(0xffffffffu, bcr, off, 16);
                if (slane >= off) { bcr = fmaf(acr, bp, bcr); acr *= ap; }
            }
            {
                float bp = __shfl_up_sync(0xffffffffu, bcr, 8, 16);
                if (slane >= 8) bcr = fmaf(acr, bp, bcr);
            }
            float bE     = __shfl_up_sync(0xffffffffu, bcr, 1, 16);
            float h_prev = (slane == 0) ? hcn : bE;     // h entering this lane
            if (slane == 15) ahc[w * 32 + seg * 16 + n].y = bcr;  // per-segment carry

            // Phase C: recompute h by direct recurrence
            float4 cv0 = Cs[n * 32 + sv0];
            float4 cv1 = Cs[n * 32 + sv1];
            float Cv[JJ] = {cv0.x, cv0.y, cv0.z, cv0.w, cv1.x, cv1.y, cv1.z, cv1.w};
            float h = h_prev;
#pragma unroll
            for (int j = 0; j < JJ; j++) {
                h = fmaf(a_[j], h, duB[j]);
                y[j] = fmaf(h, Cv[j], y[j]);
            }
        }

        // Epilogue: D-skip + SiLU gate; x reloaded (L1-hot)
        float4 z0 = *(const float4*)(zp + base);
        float4 z1 = *(const float4*)(zp + base + 4);
        float4 xr0 = *(const float4*)(xp + base);
        float4 xr1 = *(const float4*)(xp + base + 4);
        float zv[JJ] = {z0.x, z0.y, z0.z, z0.w, z1.x, z1.y, z1.z, z1.w};
        float xw[JJ] = {xr0.x, xr0.y, xr0.z, xr0.w, xr1.x, xr1.y, xr1.z, xr1.w};
        float ov[JJ];
#pragma unroll
        for (int j = 0; j < JJ; j++) {
            // silu(z) = z * (0.5 + 0.5*tanh(z/2))
            float sil = zv[j] * fmaf(0.5f, tanhf_a(0.5f * zv[j]), 0.5f);
            ov[j] = fmaf(xw[j], Dd, y[j]) * sil;
        }
        float4 o0 = {ov[0], ov[1], ov[2], ov[3]};
        float4 o1 = {ov[4], ov[5], ov[6], ov[7]};
        *(float4*)(op + base)     = o0;
        *(float4*)(op + base + 4) = o1;
    }
}

extern "C" void kernel_launch(void* const* d_in, const int* in_sizes, int n_in,
                              void* d_out, int out_size) {
    const float* x   = (const float*)d_in[0];
    const float* dt  = (const float*)d_in[1];
    const float* A   = (const float*)d_in[2];
    const float* B   = (const float*)d_in[3];
    const float* C   = (const float*)d_in[4];
    const float* D   = (const float*)d_in[5];
    const float* z   = (const float*)d_in[6];
    const float* dbb = (const float*)d_in[7];
    float* out = (float*)d_out;

    const int smem_bytes = 2048 * 16 + WARPS * 32 * 8;   // 33792
    cudaFuncSetAttribute(ssm_scan_kernel,
                         cudaFuncAttributeMaxDynamicSharedMemorySize, smem_bytes);

    dim3 grid(DD / CHB, BB);   // (192, 2) = 384 blocks of 128 threads
    ssm_scan_kernel<<<grid, 128, smem_bytes>>>(x, dt, A, B, C, D, z, dbb, out);
}

// round 15
// speedup vs baseline: 1.1620x; 1.1620x over previous
#include <cuda_runtime.h>

#define BB 2
#define DD 1536
#define LL 2048
#define NN 16
#define TL 256          // timesteps per tile
#define JJ 8            // items per lane
#define WARPS 8         // d-channels per block (1 per warp), 256 threads
#define NT (LL / TL)    // 8 tiles

typedef unsigned long long ull;

__device__ __forceinline__ float ex2f(float x) {
    float r; asm("ex2.approx.f32 %0, %1;" : "=f"(r) : "f"(x)); return r;
}
__device__ __forceinline__ float lg2f(float x) {
    float r; asm("lg2.approx.f32 %0, %1;" : "=f"(r) : "f"(x)); return r;
}
__device__ __forceinline__ float tanhf_a(float x) {
    float r; asm("tanh.approx.f32 %0, %1;" : "=f"(r) : "f"(x)); return r;
}

__device__ __forceinline__ ull pk(float lo, float hi) {
    ull r; asm("mov.b64 %0, {%1, %2};" : "=l"(r) : "f"(lo), "f"(hi)); return r;
}
__device__ __forceinline__ float lo2(ull a) {
    float x, y; asm("mov.b64 {%0, %1}, %2;" : "=f"(x), "=f"(y) : "l"(a)); return x;
}
__device__ __forceinline__ float hi2(ull a) {
    float x, y; asm("mov.b64 {%0, %1}, %2;" : "=f"(x), "=f"(y) : "l"(a)); return y;
}
__device__ __forceinline__ ull mul2(ull a, ull b) {
    ull r; asm("mul.rn.f32x2 %0, %1, %2;" : "=l"(r) : "l"(a), "l"(b)); return r;
}

// L2-cached global->shared async copy (.cg: bypass L1)
__device__ __forceinline__ void cp16(unsigned saddr, const void* gaddr) {
    asm volatile("cp.async.cg.shared.global [%0], [%1], 16;\n" :: "r"(saddr), "l"(gaddr));
}

// XOR swizzle on float4-vector index within a 64-vec (256-float) row.
__device__ __forceinline__ int swz(int v) { return v ^ ((v >> 3) & 7); }

#define L2E 1.4426950408889634f
#define LN2 0.6931471805599453f

__global__ __launch_bounds__(256, 3) void ssm_scan_kernel(
    const float* __restrict__ x_g, const float* __restrict__ dt_g,
    const float* __restrict__ A_g, const float* __restrict__ B_g,
    const float* __restrict__ C_g, const float* __restrict__ D_g,
    const float* __restrict__ z_g, const float* __restrict__ db_g,
    float* __restrict__ out_g)
{
    extern __shared__ float4 smem_dyn[];
    // [0..1024)  Bs buf0   [1024..2048) Cs buf0
    // [2048..3072) Bs buf1 [3072..4096) Cs buf1
    float2* ahc = (float2*)(smem_dyn + 4096);   // [w][n] = {A_raw, carry}

    const int b    = blockIdx.y;
    const int w    = threadIdx.x >> 5;
    const int lane = threadIdx.x & 31;
    const int d    = blockIdx.x * WARPS + w;
    const int tid  = threadIdx.x;

    const float* xp  = x_g  + (size_t)(b * DD + d) * LL;
    const float* dtp = dt_g + (size_t)(b * DD + d) * LL;
    const float* zp  = z_g  + (size_t)(b * DD + d) * LL;
    float*       op  = out_g + (size_t)(b * DD + d) * LL;

    const float4* Bg4 = (const float4*)(B_g + (size_t)b * NN * LL);
    const float4* Cg4 = (const float4*)(C_g + (size_t)b * NN * LL);

    if (lane < NN) {
        float2 v; v.x = A_g[d * NN + lane]; v.y = 0.0f;
        ahc[w * NN + lane] = v;
    }
    const float db = db_g[d];
    const float Dd = D_g[d];
    const float dbl2e = db * L2E;

    const int sv0 = swz(2 * lane);
    const int sv1 = swz(2 * lane + 1);

    // Prologue: stage tile 0 into buffer 0 via cp.async
    {
#pragma unroll
        for (int k = 0; k < 4; k++) {
            int v  = tid + k * 256;      // 0..1023
            int n  = v >> 6;
            int vc = v & 63;
            unsigned sb = (unsigned)__cvta_generic_to_shared(&smem_dyn[n * 64 + swz(vc)]);
            unsigned sc = (unsigned)__cvta_generic_to_shared(&smem_dyn[1024 + n * 64 + swz(vc)]);
            cp16(sb, Bg4 + n * (LL / 4) + vc);
            cp16(sc, Cg4 + n * (LL / 4) + vc);
        }
        asm volatile("cp.async.commit_group;\n" ::: "memory");
    }

    for (int t = 0; t < NT; t++) {
        const int l0 = t * TL;
        const int buf = (t & 1) * 2048;
        const int base = l0 + lane * JJ;

        // Per-lane global loads issued BEFORE the barrier: their DRAM latency
        // overlaps the cp.async wait + syncthreads (ptxas can't hoist past BAR).
        float4 t0 = *(const float4*)(dtp + base);
        float4 t1 = *(const float4*)(dtp + base + 4);
        float4 x0 = *(const float4*)(xp + base);
        float4 x1 = *(const float4*)(xp + base + 4);

        asm volatile("cp.async.wait_group 0;\n" ::: "memory");
        __syncthreads();   // staged data visible; prev compute done on other buffer
                           // (also orders the cross-tile smem carry writes)

        // Stage tile t+1 into the other buffer (overlaps with compute)
        if (t + 1 < NT) {
            const int nb = ((t + 1) & 1) * 2048;
            const int g0 = (t + 1) * (TL / 4);
#pragma unroll
            for (int k = 0; k < 4; k++) {
                int v  = tid + k * 256;
                int n  = v >> 6;
                int vc = v & 63;
                unsigned sb = (unsigned)__cvta_generic_to_shared(&smem_dyn[nb + n * 64 + swz(vc)]);
                unsigned sc = (unsigned)__cvta_generic_to_shared(&smem_dyn[nb + 1024 + n * 64 + swz(vc)]);
                cp16(sb, Bg4 + n * (LL / 4) + g0 + vc);
                cp16(sc, Cg4 + n * (LL / 4) + g0 + vc);
            }
            asm volatile("cp.async.commit_group;\n" ::: "memory");
        }

        const float4* Bs = smem_dyn + buf;
        const float4* Cs = smem_dyn + buf + 1024;

        float q[JJ], y[JJ], qs;
        ull du2[4];
        {
            // xv used only here; NOT kept live across the n-loop (reg headroom)
            float xv[JJ] = {x0.x, x0.y, x0.z, x0.w, x1.x, x1.y, x1.z, x1.w};
            float dv[JJ] = {t0.x, t0.y, t0.z, t0.w, t1.x, t1.y, t1.z, t1.w};
#pragma unroll
            for (int j = 0; j < JJ; j++) {
                // softplus in log2 domain: q = log2(1 + 2^((dv+db)*log2e))
                q[j] = lg2f(1.0f + ex2f(fmaf(dv[j], L2E, dbl2e)));
                y[j] = 0.0f;
            }
            qs = (q[0] + q[1]) + (q[2] + q[3]) + ((q[4] + q[5]) + (q[6] + q[7]));
#pragma unroll
            for (int p = 0; p < 4; p++)
                du2[p] = pk(q[2 * p] * LN2 * xv[2 * p],
                            q[2 * p + 1] * LN2 * xv[2 * p + 1]);
        }

#pragma unroll
        for (int n = 0; n < NN; n++) {
            const float2 ah  = ahc[w * NN + n];   // one LDS.64: {A_raw, carry}
            const float  Ar  = ah.x;
            const float  hcn = ah.y;

            float4 bv0 = Bs[n * 64 + sv0];
            float4 bv1 = Bs[n * 64 + sv1];
            ull Bv2[4] = {((ull*)&bv0)[0], ((ull*)&bv0)[1], ((ull*)&bv1)[0], ((ull*)&bv1)[1]};

            // a_ = 2^(q*Ar); aggregate product = 2^(qsum*Ar) directly
            float a_[JJ], duB[JJ];
#pragma unroll
            for (int p = 0; p < 4; p++) {
                ull duB2 = mul2(du2[p], Bv2[p]);
                duB[2 * p]     = lo2(duB2);
                duB[2 * p + 1] = hi2(duB2);
            }
#pragma unroll
            for (int j = 0; j < JJ; j++) a_[j] = ex2f(q[j] * Ar);

            // Phase A: b-aggregate chain; a-aggregate via one ex2.
            const float seed = (lane == 0) ? hcn : 0.0f;
            float acr = ex2f(qs * Ar);
            float bcr = fmaf(a_[0], seed, duB[0]);
#pragma unroll
            for (int j = 1; j < JJ; j++)
                bcr = fmaf(a_[j], bcr, duB[j]);

            // Phase B: warp inclusive scan of lane aggregates (last round b-only)
#pragma unroll
            for (int off = 1; off < 16; off <<= 1) {
                float ap = __shfl_up_sync(0xffffffffu, acr, off);
                float bp = __shfl_up_sync(0xffffffffu, bcr, off);
                if (lane >= off) { bcr = fmaf(acr, bp, bcr); acr *= ap; }
            }
            {
                float bp = __shfl_up_sync(0xffffffffu, bcr, 16);
                if (lane >= 16) bcr = fmaf(acr, bp, bcr);
            }
            float bE     = __shfl_up_sync(0xffffffffu, bcr, 1);
            float h_prev = (lane == 0) ? hcn : bE;   // true h entering this lane
            if (lane == 31) ahc[w * NN + n].y = bcr; // lane 31 holds the carry

            // Phase C: recompute h by direct recurrence
            float4 cv0 = Cs[n * 64 + sv0];
            float4 cv1 = Cs[n * 64 + sv1];
            float Cv[JJ] = {cv0.x, cv0.y, cv0.z, cv0.w, cv1.x, cv1.y, cv1.z, cv1.w};
            float h = h_prev;
#pragma unroll
            for (int j = 0; j < JJ; j++) {
                h = fmaf(a_[j], h, duB[j]);
                y[j] = fmaf(h, Cv[j], y[j]);
            }
        }

        // Epilogue: D-skip + SiLU gate; x reloaded (L1-hot) to avoid holding it
        float4 z0 = *(const float4*)(zp + base);
        float4 z1 = *(const float4*)(zp + base + 4);
        float4 xr0 = *(const float4*)(xp + base);
        float4 xr1 = *(const float4*)(xp + base + 4);
        float zv[JJ] = {z0.x, z0.y, z0.z, z0.w, z1.x, z1.y, z1.z, z1.w};
        float xw[JJ] = {xr0.x, xr0.y, xr0.z, xr0.w, xr1.x, xr1.y, xr1.z, xr1.w};
        float ov[JJ];
#pragma unroll
        for (int j = 0; j < JJ; j++) {
            // silu(z) = z * (0.5 + 0.5*tanh(z/2))
            float sil = zv[j] * fmaf(0.5f, tanhf_a(0.5f * zv[j]), 0.5f);
            ov[j] = fmaf(xw[j], Dd, y[j]) * sil;
        }
        float4 o0 = {ov[0], ov[1], ov[2], ov[3]};
        float4 o1 = {ov[4], ov[5], ov[6], ov[7]};
        *(float4*)(op + base)     = o0;
        *(float4*)(op + base + 4) = o1;
    }
}

extern "C" void kernel_launch(void* const* d_in, const int* in_sizes, int n_in,
                              void* d_out, int out_size) {
    const float* x   = (const float*)d_in[0];
    const float* dt  = (const float*)d_in[1];
    const float* A   = (const float*)d_in[2];
    const float* B   = (const float*)d_in[3];
    const float* C   = (const float*)d_in[4];
    const float* D   = (const float*)d_in[5];
    const float* z   = (const float*)d_in[6];
    const float* dbb = (const float*)d_in[7];
    float* out = (float*)d_out;

    const int smem_bytes = 4096 * 16 + WARPS * NN * 8;   // 66560
    cudaFuncSetAttribute(ssm_scan_kernel,
                         cudaFuncAttributeMaxDynamicSharedMemorySize, smem_bytes);

    dim3 grid(DD / WARPS, BB);   // (192, 2) = 384 blocks of 256 threads
    ssm_scan_kernel<<<grid, 256, smem_bytes>>>(x, dt, A, B, C, D, z, dbb, out);
}

// round 16
// speedup vs baseline: 1.1940x; 1.0276x over previous
#include <cuda_runtime.h>

#define BB 2
#define DD 1536
#define LL 2048
#define NN 16
#define TL 256          // timesteps per tile
#define JJ 8            // items per lane
#define WARPS 8         // d-channels per block (1 per warp), 256 threads
#define NT (LL / TL)    // 8 tiles

typedef unsigned long long ull;

__device__ __forceinline__ float ex2f(float x) {
    float r; asm("ex2.approx.f32 %0, %1;" : "=f"(r) : "f"(x)); return r;
}
__device__ __forceinline__ float lg2f(float x) {
    float r; asm("lg2.approx.f32 %0, %1;" : "=f"(r) : "f"(x)); return r;
}
__device__ __forceinline__ float tanhf_a(float x) {
    float r; asm("tanh.approx.f32 %0, %1;" : "=f"(r) : "f"(x)); return r;
}

__device__ __forceinline__ ull pk(float lo, float hi) {
    ull r; asm("mov.b64 %0, {%1, %2};" : "=l"(r) : "f"(lo), "f"(hi)); return r;
}
__device__ __forceinline__ float lo2(ull a) {
    float x, y; asm("mov.b64 {%0, %1}, %2;" : "=f"(x), "=f"(y) : "l"(a)); return x;
}
__device__ __forceinline__ float hi2(ull a) {
    float x, y; asm("mov.b64 {%0, %1}, %2;" : "=f"(x), "=f"(y) : "l"(a)); return y;
}
__device__ __forceinline__ ull mul2(ull a, ull b) {
    ull r; asm("mul.rn.f32x2 %0, %1, %2;" : "=l"(r) : "l"(a), "l"(b)); return r;
}

// L2-cached global->shared async copy (.cg: bypass L1)
__device__ __forceinline__ void cp16(unsigned saddr, const void* gaddr) {
    asm volatile("cp.async.cg.shared.global [%0], [%1], 16;\n" :: "r"(saddr), "l"(gaddr));
}

// Register-free L2 prefetch: warms next tile's lines, no scoreboard, no dest reg.
__device__ __forceinline__ void pf_l2(const void* gaddr) {
    asm volatile("prefetch.global.L2 [%0];\n" :: "l"(gaddr));
}

// XOR swizzle on float4-vector index within a 64-vec (256-float) row.
__device__ __forceinline__ int swz(int v) { return v ^ ((v >> 3) & 7); }

#define L2E 1.4426950408889634f
#define LN2 0.6931471805599453f

__global__ __launch_bounds__(256, 3) void ssm_scan_kernel(
    const float* __restrict__ x_g, const float* __restrict__ dt_g,
    const float* __restrict__ A_g, const float* __restrict__ B_g,
    const float* __restrict__ C_g, const float* __restrict__ D_g,
    const float* __restrict__ z_g, const float* __restrict__ db_g,
    float* __restrict__ out_g)
{
    extern __shared__ float4 smem_dyn[];
    // [0..1024)  Bs buf0   [1024..2048) Cs buf0
    // [2048..3072) Bs buf1 [3072..4096) Cs buf1
    float2* ahc = (float2*)(smem_dyn + 4096);   // [w][n] = {A_raw, carry}

    const int b    = blockIdx.y;
    const int w    = threadIdx.x >> 5;
    const int lane = threadIdx.x & 31;
    const int d    = blockIdx.x * WARPS + w;
    const int tid  = threadIdx.x;

    const float* xp  = x_g  + (size_t)(b * DD + d) * LL;
    const float* dtp = dt_g + (size_t)(b * DD + d) * LL;
    const float* zp  = z_g  + (size_t)(b * DD + d) * LL;
    float*       op  = out_g + (size_t)(b * DD + d) * LL;

    const float4* Bg4 = (const float4*)(B_g + (size_t)b * NN * LL);
    const float4* Cg4 = (const float4*)(C_g + (size_t)b * NN * LL);

    if (lane < NN) {
        float2 v; v.x = A_g[d * NN + lane]; v.y = 0.0f;
        ahc[w * NN + lane] = v;
    }
    const float db = db_g[d];
    const float Dd = D_g[d];
    const float dbl2e = db * L2E;

    const int sv0 = swz(2 * lane);
    const int sv1 = swz(2 * lane + 1);

    // Prologue: stage tile 0 into buffer 0 via cp.async
    {
#pragma unroll
        for (int k = 0; k < 4; k++) {
            int v  = tid + k * 256;      // 0..1023
            int n  = v >> 6;
            int vc = v & 63;
            unsigned sb = (unsigned)__cvta_generic_to_shared(&smem_dyn[n * 64 + swz(vc)]);
            unsigned sc = (unsigned)__cvta_generic_to_shared(&smem_dyn[1024 + n * 64 + swz(vc)]);
            cp16(sb, Bg4 + n * (LL / 4) + vc);
            cp16(sc, Cg4 + n * (LL / 4) + vc);
        }
        asm volatile("cp.async.commit_group;\n" ::: "memory");
    }

    for (int t = 0; t < NT; t++) {
        const int l0 = t * TL;
        const int buf = (t & 1) * 2048;

        asm volatile("cp.async.wait_group 0;\n" ::: "memory");
        __syncthreads();   // staged data visible; prev compute done on other buffer
                           // (also orders the cross-tile smem carry writes)

        // Stage tile t+1 into the other buffer (overlaps with compute),
        // and warm next tile's per-warp dt/x/z lines into L2 (reg-free).
        if (t + 1 < NT) {
            const int nb = ((t + 1) & 1) * 2048;
            const int g0 = (t + 1) * (TL / 4);
#pragma unroll
            for (int k = 0; k < 4; k++) {
                int v  = tid + k * 256;
                int n  = v >> 6;
                int vc = v & 63;
                unsigned sb = (unsigned)__cvta_generic_to_shared(&smem_dyn[nb + n * 64 + swz(vc)]);
                unsigned sc = (unsigned)__cvta_generic_to_shared(&smem_dyn[nb + 1024 + n * 64 + swz(vc)]);
                cp16(sb, Bg4 + n * (LL / 4) + g0 + vc);
                cp16(sc, Cg4 + n * (LL / 4) + g0 + vc);
            }
            asm volatile("cp.async.commit_group;\n" ::: "memory");

            const int nbase = l0 + TL + lane * JJ;
            pf_l2(dtp + nbase);
            pf_l2(xp + nbase);
            pf_l2(zp + nbase);
        }

        const float4* Bs = smem_dyn + buf;
        const float4* Cs = smem_dyn + buf + 1024;

        // Per-lane loads for its 8 contiguous timesteps
        const int base = l0 + lane * JJ;
        float4 t0 = *(const float4*)(dtp + base);
        float4 t1 = *(const float4*)(dtp + base + 4);
        float4 x0 = *(const float4*)(xp + base);
        float4 x1 = *(const float4*)(xp + base + 4);

        float q[JJ], y[JJ], qs;
        ull du2[4];
        {
            // xv used only here; NOT kept live across the n-loop (reg headroom)
            float xv[JJ] = {x0.x, x0.y, x0.z, x0.w, x1.x, x1.y, x1.z, x1.w};
            float dv[JJ] = {t0.x, t0.y, t0.z, t0.w, t1.x, t1.y, t1.z, t1.w};
#pragma unroll
            for (int j = 0; j < JJ; j++) {
                // softplus in log2 domain: q = log2(1 + 2^((dv+db)*log2e))
                q[j] = lg2f(1.0f + ex2f(fmaf(dv[j], L2E, dbl2e)));
                y[j] = 0.0f;
            }
            qs = (q[0] + q[1]) + (q[2] + q[3]) + ((q[4] + q[5]) + (q[6] + q[7]));
#pragma unroll
            for (int p = 0; p < 4; p++)
                du2[p] = pk(q[2 * p] * LN2 * xv[2 * p],
                            q[2 * p + 1] * LN2 * xv[2 * p + 1]);
        }

#pragma unroll
        for (int n = 0; n < NN; n++) {
            const float2 ah  = ahc[w * NN + n];   // one LDS.64: {A_raw, carry}
            const float  Ar  = ah.x;
            const float  hcn = ah.y;

            float4 bv0 = Bs[n * 64 + sv0];
            float4 bv1 = Bs[n * 64 + sv1];
            ull Bv2[4] = {((ull*)&bv0)[0], ((ull*)&bv0)[1], ((ull*)&bv1)[0], ((ull*)&bv1)[1]};

            // a_ = 2^(q*Ar); aggregate product = 2^(qsum*Ar) directly
            float a_[JJ], duB[JJ];
#pragma unroll
            for (int p = 0; p < 4; p++) {
                ull duB2 = mul2(du2[p], Bv2[p]);
                duB[2 * p]     = lo2(duB2);
                duB[2 * p + 1] = hi2(duB2);
            }
#pragma unroll
            for (int j = 0; j < JJ; j++) a_[j] = ex2f(q[j] * Ar);

            // Phase A: b-aggregate chain; a-aggregate via one ex2.
            const float seed = (lane == 0) ? hcn : 0.0f;
            float acr = ex2f(qs * Ar);
            float bcr = fmaf(a_[0], seed, duB[0]);
#pragma unroll
            for (int j = 1; j < JJ; j++)
                bcr = fmaf(a_[j], bcr, duB[j]);

            // Phase B: warp inclusive scan of lane aggregates (last round b-only)
#pragma unroll
            for (int off = 1; off < 16; off <<= 1) {
                float ap = __shfl_up_sync(0xffffffffu, acr, off);
                float bp = __shfl_up_sync(0xffffffffu, bcr, off);
                if (lane >= off) { bcr = fmaf(acr, bp, bcr); acr *= ap; }
            }
            {
                float bp = __shfl_up_sync(0xffffffffu, bcr, 16);
                if (lane >= 16) bcr = fmaf(acr, bp, bcr);
            }
            float bE     = __shfl_up_sync(0xffffffffu, bcr, 1);
            float h_prev = (lane == 0) ? hcn : bE;   // true h entering this lane
            if (lane == 31) ahc[w * NN + n].y = bcr; // lane 31 holds the carry

            // Phase C: recompute h by direct recurrence
            float4 cv0 = Cs[n * 64 + sv0];
            float4 cv1 = Cs[n * 64 + sv1];
            float Cv[JJ] = {cv0.x, cv0.y, cv0.z, cv0.w, cv1.x, cv1.y, cv1.z, cv1.w};
            float h = h_prev;
#pragma unroll
            for (int j = 0; j < JJ; j++) {
                h = fmaf(a_[j], h, duB[j]);
                y[j] = fmaf(h, Cv[j], y[j]);
            }
        }

        // Epilogue: D-skip + SiLU gate; x reloaded (L1-hot) to avoid holding it
        float4 z0 = *(const float4*)(zp + base);
        float4 z1 = *(const float4*)(zp + base + 4);
        float4 xr0 = *(const float4*)(xp + base);
        float4 xr1 = *(const float4*)(xp + base + 4);
        float zv[JJ] = {z0.x, z0.y, z0.z, z0.w, z1.x, z1.y, z1.z, z1.w};
        float xw[JJ] = {xr0.x, xr0.y, xr0.z, xr0.w, xr1.x, xr1.y, xr1.z, xr1.w};
        float ov[JJ];
#pragma unroll
        for (int j = 0; j < JJ; j++) {
            // silu(z) = z * (0.5 + 0.5*tanh(z/2))
            float sil = zv[j] * fmaf(0.5f, tanhf_a(0.5f * zv[j]), 0.5f);
            ov[j] = fmaf(xw[j], Dd, y[j]) * sil;
        }
        float4 o0 = {ov[0], ov[1], ov[2], ov[3]};
        float4 o1 = {ov[4], ov[5], ov[6], ov[7]};
        *(float4*)(op + base)     = o0;
        *(float4*)(op + base + 4) = o1;
    }
}

extern "C" void kernel_launch(void* const* d_in, const int* in_sizes, int n_in,
                              void* d_out, int out_size) {
    const float* x   = (const float*)d_in[0];
    const float* dt  = (const float*)d_in[1];
    const float* A   = (const float*)d_in[2];
    const float* B   = (const float*)d_in[3];
    const float* C   = (const float*)d_in[4];
    const float* D   = (const float*)d_in[5];
    const float* z   = (const float*)d_in[6];
    const float* dbb = (const float*)d_in[7];
    float* out = (float*)d_out;

    const int smem_bytes = 4096 * 16 + WARPS * NN * 8;   // 66560
    cudaFuncSetAttribute(ssm_scan_kernel,
                         cudaFuncAttributeMaxDynamicSharedMemorySize, smem_bytes);

    dim3 grid(DD / WARPS, BB);   // (192, 2) = 384 blocks of 256 threads
    ssm_scan_kernel<<<grid, 256, smem_bytes>>>(x, dt, A, B, C, D, z, dbb, out);
}